// round 17
// baseline (speedup 1.0000x reference)
#include <cuda_runtime.h>
#include <cstdint>

#define HID   8
#define OBS   8
#define CTRL  2
#define WIDTH 256
#define BB    8192
#define TT    256
#define CH    8
#define NCH   (TT / CH)      // 32 chunks

#define E_BLK 64             // k_dec elements per block
#define A0S   68             // s_a0 row stride (floats): 64 elems + 4 pad, 16B-aligned slices
#define SMEM_DEC ((WIDTH * A0S + E_BLK * 12 + 16 * 8) * 4)   // 73216 bytes

// ---------------- scratch (no allocations allowed) ----------------
__device__ float g_h[BB * HID];            // final hidden states [B,8]
__device__ float g_w1t[WIDTH * WIDTH];     // W1 transposed: w1t[k*256 + o] = W1[o][k]

// ---------------- f32x2 helpers ----------------
typedef unsigned long long u64;

__device__ __forceinline__ u64 pack2(float lo, float hi) {
    u64 r;
    asm("mov.b64 %0, {%1, %2};" : "=l"(r) : "r"(__float_as_uint(lo)), "r"(__float_as_uint(hi)));
    return r;
}
__device__ __forceinline__ void unpack2(u64 v, float& lo, float& hi) {
    unsigned a, b;
    asm("mov.b64 {%0, %1}, %2;" : "=r"(a), "=r"(b) : "l"(v));
    lo = __uint_as_float(a);
    hi = __uint_as_float(b);
}
__device__ __forceinline__ u64 ffma2(u64 a, u64 b, u64 c) {
    u64 d;
    asm("fma.rn.f32x2 %0, %1, %2, %3;" : "=l"(d) : "l"(a), "l"(b), "l"(c));
    return d;
}

// ---------------- kernel 1: Wilson-Cowan recurrence (+ fused W1 transpose) ----------------
// 4 lanes per batch element; lane s owns output rows {2s, 2s+1}.
// Round-13 fit: the old per-element broadcast LDGs were L1tex-wavefront bound
// (24 wf/step/warp). Fix: coalesced chunk loads (8 steps) -> smem, double
// buffered; per-step reads are broadcast LDS (conflict-free strides).
__global__ void __launch_bounds__(128) k_recur(
    const float* __restrict__ state_seq,    // [B,T,8]
    const float* __restrict__ control_seq,  // [B,T,2]
    const float* __restrict__ W_A,          // [8,8]
    const float* __restrict__ W_B,          // [8,10]
    const float* __restrict__ W1)           // [256,256]
{
    int tid = threadIdx.x;
    int gt = blockIdx.x * 128 + tid;        // B*4 = 32768 threads

    // fused one-time transpose (2 elements per thread)
    {
        int idx = gt * 2;
        g_w1t[idx]     = W1[(idx & 255) * WIDTH + (idx >> 8)];
        int idx1 = idx + 1;
        g_w1t[idx1]    = W1[(idx1 & 255) * WIDTH + (idx1 >> 8)];
    }

    int w = tid >> 5;        // warp in block (0..3)
    int l = tid & 31;        // lane
    int g = l >> 2;          // element group within warp (0..7)
    int s = l & 3;           // sub-lane: owns rows 2s,2s+1; also load quarter
    int b = blockIdx.x * 32 + w * 8 + g;    // this lane's batch element

    // smem staging: [warp][buf][elem-stride 68/20 floats]
    __shared__ float s_st[4][2][8 * 68];    // state: 8 elems x (8 steps x 8 floats + pad)
    __shared__ float s_ct[4][2][8 * 20];    // ctrl:  8 elems x (8 steps x 2 floats + pad)

    float wa0[HID], wa1[HID], wb0[OBS + CTRL], wb1[OBS + CTRL];
#pragma unroll
    for (int j = 0; j < HID; j++) {
        wa0[j] = W_A[(2 * s) * HID + j];
        wa1[j] = W_A[(2 * s + 1) * HID + j];
    }
#pragma unroll
    for (int j = 0; j < OBS + CTRL; j++) {
        wb0[j] = W_B[(2 * s) * (OBS + CTRL) + j];
        wb1[j] = W_B[(2 * s + 1) * (OBS + CTRL) + j];
    }

    const float* spL = state_seq + (size_t)b * TT * OBS;    // this lane loads its own elem
    const float* cpL = control_seq + (size_t)b * TT * CTRL;

    // chunk staging registers (coalesced loads: 64B state + 16B ctrl per lane)
    float4 r0, r1, r2, r3, rc;

    // load chunk starting at step t0 into registers
    auto load_chunk = [&](int t0) {
        const float* p = spL + t0 * 8 + s * 4;
        r0 = *(const float4*)(p);
        r1 = *(const float4*)(p + 16);
        r2 = *(const float4*)(p + 32);
        r3 = *(const float4*)(p + 48);
        rc = *(const float4*)(cpL + t0 * 2 + s * 4);
    };
    // store staged registers into smem buffer
    auto store_chunk = [&](int buf) {
        float* st = &s_st[w][buf][g * 68 + s * 4];
        *(float4*)(st)      = r0;
        *(float4*)(st + 16) = r1;
        *(float4*)(st + 32) = r2;
        *(float4*)(st + 48) = r3;
        *(float4*)(&s_ct[w][buf][g * 20 + s * 4]) = rc;
    };

    float ha = 0.0f, hb = 0.0f;   // h[2s], h[2s+1]

    load_chunk(0);
    store_chunk(0);
    __syncwarp();

    for (int ch = 0; ch < NCH; ch++) {
        int chn = (ch + 1 < NCH) ? ch + 1 : ch;
        load_chunk(chn * CH);                       // prefetch next chunk

        const float* stc = &s_st[w][ch & 1][g * 68];
        const float* ctc = &s_ct[w][ch & 1][g * 20];

#pragma unroll
        for (int t = 0; t < CH; t++) {
            float4 xa = *(const float4*)(stc + t * 8);
            float4 xb = *(const float4*)(stc + t * 8 + 4);
            float2 c  = *(const float2*)(ctc + t * 2);

            float h0 = __shfl_sync(0xffffffffu, ha, 0, 4);
            float h1 = __shfl_sync(0xffffffffu, hb, 0, 4);
            float h2 = __shfl_sync(0xffffffffu, ha, 1, 4);
            float h3 = __shfl_sync(0xffffffffu, hb, 1, 4);
            float h4 = __shfl_sync(0xffffffffu, ha, 2, 4);
            float h5 = __shfl_sync(0xffffffffu, hb, 2, 4);
            float h6 = __shfl_sync(0xffffffffu, ha, 3, 4);
            float h7 = __shfl_sync(0xffffffffu, hb, 3, 4);

            float a0 = wb0[OBS] * c.x + wb0[OBS + 1] * c.y;
            a0 += wb0[0] * xa.x + wb0[1] * xa.y + wb0[2] * xa.z + wb0[3] * xa.w;
            a0 += wb0[4] * xb.x + wb0[5] * xb.y + wb0[6] * xb.z + wb0[7] * xb.w;
            a0 += wa0[0] * h0 + wa0[1] * h1 + wa0[2] * h2 + wa0[3] * h3;
            a0 += wa0[4] * h4 + wa0[5] * h5 + wa0[6] * h6 + wa0[7] * h7;

            float a1 = wb1[OBS] * c.x + wb1[OBS + 1] * c.y;
            a1 += wb1[0] * xa.x + wb1[1] * xa.y + wb1[2] * xa.z + wb1[3] * xa.w;
            a1 += wb1[4] * xb.x + wb1[5] * xb.y + wb1[6] * xb.z + wb1[7] * xb.w;
            a1 += wa1[0] * h0 + wa1[1] * h1 + wa1[2] * h2 + wa1[3] * h3;
            a1 += wa1[4] * h4 + wa1[5] * h5 + wa1[6] * h6 + wa1[7] * h7;

            ha = __fdividef(1.0f, 1.0f + __expf(-a0));
            hb = __fdividef(1.0f, 1.0f + __expf(-a1));
        }

        store_chunk((ch & 1) ^ 1);                  // stage next chunk
        __syncwarp();
    }

    g_h[b * HID + 2 * s]     = ha;
    g_h[b * HID + 2 * s + 1] = hb;
}

// ---------------- kernel 2: decoder MLP (10->256->256->1), layer2 fused ----------------
// 64 elements/block (halves redundant weight traffic per element vs 32),
// 512 threads, 128 blocks, 16 u64 accumulators (no reg cap -> no spill).
// Thread (og,eg): og = tid&63 -> outputs 4og..4og+3 ; eg = tid>>6 -> elems 8eg..8eg+7.
__global__ void __launch_bounds__(512) k_dec(
    const float* __restrict__ control,  // [B,2]
    const float* __restrict__ W0,       // [256,10]
    const float* __restrict__ b0,       // [256]
    const float* __restrict__ b1,       // [256]
    const float* __restrict__ W2,       // [1,256]
    const float* __restrict__ b2,       // [1]
    float* __restrict__ out)            // [B]
{
    extern __shared__ float sm[];
    float* s_a0  = sm;                         // [256][A0S]
    float* s_x   = sm + WIDTH * A0S;           // [64][12]
    float* s_red = s_x + E_BLK * 12;           // [16][8]

    int tid = threadIdx.x;
    int be0 = blockIdx.x * E_BLK;

    // stage concat(h, control) for 64 elements (640 values)
    for (int idx = tid; idx < E_BLK * 10; idx += 512) {
        int e = idx / 10, j = idx % 10;
        float v = (j < 8) ? g_h[(be0 + e) * HID + j]
                          : control[(be0 + e) * CTRL + (j - 8)];
        s_x[e * 12 + j] = v;
    }
    __syncthreads();

    // ---- layer 0: neuron n = tid&255, half = tid>>8 -> 32 elements each ----
    {
        int n = tid & 255;
        int ebase = (tid >> 8) * 32;
        float wr[10];
#pragma unroll
        for (int j = 0; j < 10; j++) wr[j] = W0[n * 10 + j];
        float bias = b0[n];
#pragma unroll 4
        for (int e2 = 0; e2 < 32; e2++) {
            int e = ebase + e2;
            float4 x0 = *(const float4*)(s_x + e * 12);
            float4 x1 = *(const float4*)(s_x + e * 12 + 4);
            float2 x2 = *(const float2*)(s_x + e * 12 + 8);
            float a = bias;
            a += wr[0] * x0.x + wr[1] * x0.y + wr[2] * x0.z + wr[3] * x0.w;
            a += wr[4] * x1.x + wr[5] * x1.y + wr[6] * x1.z + wr[7] * x1.w;
            a += wr[8] * x2.x + wr[9] * x2.y;
            s_a0[n * A0S + e] = fmaxf(a, 0.0f);
        }
    }
    __syncthreads();

    // ---- layer 1 (f32x2) + fused layer 2 ----
    int og = tid & 63;
    int eg = tid >> 6;      // 0..7 (uniform within a warp)
    int e0 = eg * 8;        // 8 elements = 4 f32x2 pairs

    u64 acc[16];            // [i out 0..3][p pair 0..3]
#pragma unroll
    for (int r = 0; r < 16; r++) acc[r] = 0ull;

    const float4* wbase = (const float4*)g_w1t;   // row k: 64 float4s over outputs

#pragma unroll 2
    for (int k = 0; k < WIDTH; k++) {
        float4 wv = __ldg(&wbase[k * 64 + og]);   // coalesced LDG.128 (4 wf/warp)
        u64 wp0 = pack2(wv.x, wv.x);
        u64 wp1 = pack2(wv.y, wv.y);
        u64 wp2 = pack2(wv.z, wv.z);
        u64 wp3 = pack2(wv.w, wv.w);
        // two broadcast LDS.128 (same address across warp), 16B-aligned
        const ulonglong2* ar = (const ulonglong2*)(s_a0 + k * A0S + e0);
        ulonglong2 aa = ar[0];                    // elems e0..e0+3
        ulonglong2 ab = ar[1];                    // elems e0+4..e0+7
        u64 ap[4] = { aa.x, aa.y, ab.x, ab.y };
#pragma unroll
        for (int p = 0; p < 4; p++) {
            acc[0 * 4 + p] = ffma2(wp0, ap[p], acc[0 * 4 + p]);
            acc[1 * 4 + p] = ffma2(wp1, ap[p], acc[1 * 4 + p]);
            acc[2 * 4 + p] = ffma2(wp2, ap[p], acc[2 * 4 + p]);
            acc[3 * 4 + p] = ffma2(wp3, ap[p], acc[3 * 4 + p]);
        }
    }

    // epilogue: bias + relu + W2 scale -> per-element partials q[0..7]
    float q[8];
#pragma unroll
    for (int r = 0; r < 8; r++) q[r] = 0.0f;

#pragma unroll
    for (int i = 0; i < 4; i++) {
        int o = og * 4 + i;
        float bv = b1[o];
        float wv = W2[o];
#pragma unroll
        for (int p = 0; p < 4; p++) {
            float lo, hi;
            unpack2(acc[i * 4 + p], lo, hi);
            q[2 * p]     += fmaxf(lo + bv, 0.0f) * wv;
            q[2 * p + 1] += fmaxf(hi + bv, 0.0f) * wv;
        }
    }

    // warp butterfly reduce (each warp has a single eg; og spans 32 values)
#pragma unroll
    for (int off = 16; off; off >>= 1) {
#pragma unroll
        for (int r = 0; r < 8; r++)
            q[r] += __shfl_xor_sync(0xffffffffu, q[r], off);
    }
    int warp = tid >> 5;    // 0..15; warps 2m,2m+1 share eg=m (og halves)
    if ((tid & 31) == 0) {
#pragma unroll
        for (int r = 0; r < 8; r++) s_red[warp * 8 + r] = q[r];
    }
    __syncthreads();

    // combine the two warps per eg + bias, write output
    if (tid < E_BLK) {
        int e = tid;
        int m = e >> 3;                     // eg
        int r = e & 7;
        float val = s_red[(2 * m) * 8 + r] + s_red[(2 * m + 1) * 8 + r] + b2[0];
        out[be0 + e] = val;
    }
}

// ---------------- launch ----------------
extern "C" void kernel_launch(void* const* d_in, const int* in_sizes, int n_in,
                              void* d_out, int out_size)
{
    const float* state_seq   = (const float*)d_in[0];
    const float* control_seq = (const float*)d_in[1];
    const float* control     = (const float*)d_in[2];
    const float* W_A         = (const float*)d_in[3];
    const float* W_B         = (const float*)d_in[4];
    const float* W0          = (const float*)d_in[5];
    const float* b0          = (const float*)d_in[6];
    const float* W1          = (const float*)d_in[7];
    const float* b1          = (const float*)d_in[8];
    const float* W2          = (const float*)d_in[9];
    const float* b2          = (const float*)d_in[10];
    float* out = (float*)d_out;

    cudaFuncSetAttribute(k_dec, cudaFuncAttributeMaxDynamicSharedMemorySize, SMEM_DEC);

    k_recur<<<BB * 4 / 128, 128>>>(state_seq, control_seq, W_A, W_B, W1);
    k_dec<<<BB / E_BLK, 512, SMEM_DEC>>>(control, W0, b0, b1, W2, b2, out);
}